// round 2
// baseline (speedup 1.0000x reference)
#include <cuda_runtime.h>

typedef unsigned long long u64;

#define NBMAX 28          // batches per CTA
#define NPMAX 14          // batch pairs per CTA
#define HDIM  64
#define GDIM  256         // 4*HDIM gate rows
#define IDIM  8

// ---- packed f32x2 helpers (Blackwell sm_100a) ----
__device__ __forceinline__ u64 ffma2(u64 a, u64 b, u64 c) {
    u64 r;
    asm("fma.rn.f32x2 %0, %1, %2, %3;" : "=l"(r) : "l"(a), "l"(b), "l"(c));
    return r;
}
__device__ __forceinline__ u64 pack2(float x, float y) {
    u64 r;
    asm("mov.b64 %0, {%1, %2};" : "=l"(r) : "f"(x), "f"(y));
    return r;
}

// ---- activations: __expf is MUFU-based, ~1e-7 rel err (protects 1e-3 budget) ----
__device__ __forceinline__ float sigm_f(float x) {
    return 1.0f / (1.0f + __expf(-x));
}
__device__ __forceinline__ float tanh_f(float x) {
    // tanh(x) = 2*sigmoid(2x) - 1
    return fmaf(2.0f, 1.0f / (1.0f + __expf(-2.0f * x)), -1.0f);
}

__global__ void __launch_bounds__(256, 1) lstm_persistent_kernel(
    const float* __restrict__ x,      // [B, T, I]
    const float* __restrict__ Wih,    // [4H, I]
    const float* __restrict__ Whh,    // [4H, H]
    const float* __restrict__ bih,    // [4H]
    const float* __restrict__ bhh,    // [4H]
    const float* __restrict__ Wfc,    // [1, H]
    const float* __restrict__ bfc,    // [1]
    float* __restrict__ out,          // [B, 1]
    int B, int T)
{
    // SMEM: packed-by-batch-pair buffers. u64 = (float b_even, float b_odd)
    __shared__ __align__(16) u64 gates[NPMAX * GDIM];   // 28 KB
    __shared__ __align__(16) u64 hbuf[NPMAX * HDIM];    // 7 KB
    __shared__ __align__(16) u64 xs[2][NPMAX * IDIM];   // 1.75 KB (double buffer)

    const int tid = threadIdx.x;
    const int b0  = blockIdx.x * NBMAX;
    const int nb  = min(NBMAX, B - b0);
    const int np  = (nb + 1) >> 1;          // batch pairs
    const int ntask = np * 2 * HDIM;        // pointwise tasks
    const int nx  = nb * IDIM;              // x scalars per step

    // ---- preload weights into registers, packed (w,w) ----
    u64 whh2[HDIM];
#pragma unroll
    for (int k = 0; k < HDIM; ++k) {
        float w = Whh[tid * HDIM + k];
        whh2[k] = pack2(w, w);
    }
    u64 wih2[IDIM];
#pragma unroll
    for (int i = 0; i < IDIM; ++i) {
        float w = Wih[tid * IDIM + i];
        wih2[i] = pack2(w, w);
    }
    const float bsum = bih[tid] + bhh[tid];
    const u64 bias2 = pack2(bsum, bsum);

    // ---- zero h, x buffers ----
    for (int idx = tid; idx < NPMAX * HDIM; idx += 256) hbuf[idx] = 0ull;
    for (int idx = tid; idx < NPMAX * IDIM; idx += 256) { xs[0][idx] = 0ull; xs[1][idx] = 0ull; }

    // pointwise cell state lives in registers: task idx = tid + 256*r
    float creg[7];
#pragma unroll
    for (int r = 0; r < 7; ++r) creg[r] = 0.0f;

    // ---- load x(t=0) into xs[0] ----
    int xp = 0, xe = 0, xi = 0;
    if (tid < nx) {
        xp = tid >> 4;            // pair
        xe = (tid >> 3) & 1;      // half within pair
        xi = tid & 7;             // input feature
        float v = x[((size_t)(b0 + 2 * xp + xe) * T) * IDIM + xi];
        ((float*)&xs[0][xp * IDIM + xi])[xe] = v;
    }
    __syncthreads();

    const float* gatesf = (const float*)gates;
    float* hbuff = (float*)hbuf;

    for (int t = 0; t < T; ++t) {
        // prefetch x(t+1) into a register (latency hidden by matvec)
        float xn = 0.0f;
        const bool do_x = (t + 1 < T) && (tid < nx);
        if (do_x)
            xn = x[((size_t)(b0 + 2 * xp + xe) * T + (t + 1)) * IDIM + xi];

        const u64* xcur = xs[t & 1];

        // ---- matvec: gate[j] = bias + Wih[j,:].x + Whh[j,:].h, two pairs at a time ----
        for (int p = 0; p < np; p += 2) {
            const bool two = (p + 1 < np);
            u64 a0 = bias2, a1 = bias2;
            const u64* h0 = hbuf + p * HDIM;
            const u64* h1 = hbuf + (p + 1) * HDIM;
            const u64* x0 = xcur + p * IDIM;
            const u64* x1 = xcur + (p + 1) * IDIM;
#pragma unroll
            for (int i = 0; i < IDIM; i += 2) {
                ulonglong2 xv0 = *(const ulonglong2*)(x0 + i);
                a0 = ffma2(xv0.x, wih2[i], a0);
                a0 = ffma2(xv0.y, wih2[i + 1], a0);
                if (two) {
                    ulonglong2 xv1 = *(const ulonglong2*)(x1 + i);
                    a1 = ffma2(xv1.x, wih2[i], a1);
                    a1 = ffma2(xv1.y, wih2[i + 1], a1);
                }
            }
#pragma unroll
            for (int k = 0; k < HDIM; k += 2) {
                ulonglong2 hv0 = *(const ulonglong2*)(h0 + k);
                a0 = ffma2(hv0.x, whh2[k], a0);
                a0 = ffma2(hv0.y, whh2[k + 1], a0);
                if (two) {
                    ulonglong2 hv1 = *(const ulonglong2*)(h1 + k);
                    a1 = ffma2(hv1.x, whh2[k], a1);
                    a1 = ffma2(hv1.y, whh2[k + 1], a1);
                }
            }
            gates[p * GDIM + tid] = a0;
            if (two) gates[(p + 1) * GDIM + tid] = a1;
        }

        // stash prefetched x into the other buffer (visible after barrier)
        if (do_x)
            ((float*)&xs[(t + 1) & 1][xp * IDIM + xi])[xe] = xn;

        __syncthreads();

        // ---- pointwise: i,f,g,o -> c,h ----
#pragma unroll
        for (int r = 0; r < 7; ++r) {
            const int idx = tid + 256 * r;
            if (idx < ntask) {
                const int p = idx >> 7;        // /128
                const int e = (idx >> 6) & 1;
                const int u = idx & 63;
                const int base = p * GDIM;
                float gi = gatesf[(base + u) * 2 + e];
                float gf = gatesf[(base + 64 + u) * 2 + e];
                float gg = gatesf[(base + 128 + u) * 2 + e];
                float go = gatesf[(base + 192 + u) * 2 + e];
                float iv = sigm_f(gi);
                float fv = sigm_f(gf);
                float gv = tanh_f(gg);
                float ov = sigm_f(go);
                float c  = fmaf(fv, creg[r], iv * gv);
                creg[r] = c;
                hbuff[(p * HDIM + u) * 2 + e] = ov * tanh_f(c);
            }
        }
        __syncthreads();
    }

    // ---- final FC: out[b] = h_T . Wfc + bfc ----
    if (tid < nb) {
        const int p = tid >> 1, e = tid & 1;
        float s = bfc[0];
#pragma unroll
        for (int u = 0; u < HDIM; ++u)
            s = fmaf(hbuff[(p * HDIM + u) * 2 + e], Wfc[u], s);
        out[b0 + tid] = s;
    }
}

extern "C" void kernel_launch(void* const* d_in, const int* in_sizes, int n_in,
                              void* d_out, int out_size) {
    const float* x    = (const float*)d_in[0];
    const float* Wih  = (const float*)d_in[1];
    const float* Whh  = (const float*)d_in[2];
    const float* bih  = (const float*)d_in[3];
    const float* bhh  = (const float*)d_in[4];
    const float* Wfc  = (const float*)d_in[5];
    const float* bfc  = (const float*)d_in[6];
    float* out = (float*)d_out;

    const int B = out_size;                   // O = 1
    const int T = in_sizes[0] / (B * IDIM);

    const int grid = (B + NBMAX - 1) / NBMAX;
    lstm_persistent_kernel<<<grid, 256>>>(x, Wih, Whh, bih, bhh, Wfc, bfc, out, B, T);
}